// round 9
// baseline (speedup 1.0000x reference)
#include <cuda_runtime.h>
#include <cuda_bf16.h>

// UmbralCone: hyperbolic cone distance.
//  weight: f32 [SIZE=100000, 32]   (d_in[0])
//  inputs: i32 [B=16384, 50]       (d_in[1])
//  out:    f32 [B, 49]
//
// Persistent software-pipelined version:
//  grid=1024 blocks x 128 threads; each block loops over ~8 tiles (RPB=2
//  batch rows per tile) with DOUBLE-BUFFERED smem: cp.async for tile t+1
//  issued before waiting on tile t, so the gather L2 latency is hidden
//  behind tile t's compute. wait_group 1 => all groups except the newest done.
//
//  Per tile: gather 100 weight rows (128B) into padded row-major SMEM
//  (stride 9 float4 = 144B; conflict-free STS.128/LDS.128), 2 threads do
//  parent scalars, then one thread per (row, child) pair does dot/norm+tail.

#define RPB   2
#define KTOT  50
#define NCH   49
#define NROWS (RPB * KTOT)   // 100
#define RSTR  9              // float4 stride per row (144B)
#define GRIDN 1024

__device__ __forceinline__ float arcosh_fast(float x) {
    x = fmaxf(x, 1.0f + 1e-7f);
    return __logf(x + sqrtf(x * x - 1.0f));
}

__device__ __forceinline__ void cp16(const float4* dst_smem, const float4* src_gmem) {
    unsigned dst = (unsigned)__cvta_generic_to_shared(dst_smem);
    asm volatile("cp.async.cg.shared.global [%0], [%1], 16;\n"
                 :: "r"(dst), "l"(src_gmem));
}

__global__ __launch_bounds__(128, 7)
void umbral_cone_kernel(const float* __restrict__ weight,
                        const int* __restrict__ inputs,
                        float* __restrict__ out,
                        int B, int ntiles) {
    __shared__ __align__(16) float4 s4[2][NROWS * RSTR];  // 2 x 14400 B
    __shared__ __align__(16) float4 srow[RPB * 2];        // per-row parent scalars

    const int tid = threadIdx.x;
    const int g0  = tid >> 3;     // gathered-row id at u=0  (0..15)
    const int fi  = tid & 7;      // float4 lane within the 128B row

    // ---- gather one tile into buffer buf ----
    auto gather = [&](int tile, int buf) {
        const int row0 = tile * RPB;
        const long long gbase = (long long)row0 * KTOT;
        float4* sb = s4[buf];
        if (row0 + RPB <= B) {
            int idxv[7];
            #pragma unroll
            for (int u = 0; u < 7; u++) {
                int g = g0 + 16 * u;
                if (u < 6 || g0 < NROWS - 96)           // u==6: g0 < 4
                    idxv[u] = inputs[gbase + g];
            }
            #pragma unroll
            for (int u = 0; u < 7; u++) {
                int g = g0 + 16 * u;
                if (u < 6 || g0 < NROWS - 96)
                    cp16(&sb[g * RSTR + fi],
                         (const float4*)(weight + (long long)idxv[u] * 32) + fi);
            }
        } else {
            const int lim = (B - row0) * KTOT;
            #pragma unroll
            for (int u = 0; u < 7; u++) {
                int g = g0 + 16 * u;
                if (g < lim && g < NROWS) {
                    int idx = inputs[gbase + g];
                    cp16(&sb[g * RSTR + fi],
                         (const float4*)(weight + (long long)idx * 32) + fi);
                }
            }
        }
    };

    const int t0 = blockIdx.x;

    // Prologue: start tile t0 into buf 0.
    if (t0 < ntiles) gather(t0, 0);
    asm volatile("cp.async.commit_group;\n");

    int buf = 0;
    for (int tile = t0; tile < ntiles; tile += GRIDN, buf ^= 1) {
        // Protect the buffer the upcoming cp.asyncs will overwrite
        // (last read 2 iterations ago; barrier also separates from prev 2b).
        __syncthreads();

        // Issue next tile's gather into the other buffer.
        int nxt = tile + GRIDN;
        if (nxt < ntiles) gather(nxt, buf ^ 1);
        asm volatile("cp.async.commit_group;\n");

        // Wait for current tile (all groups but the newest are complete).
        asm volatile("cp.async.wait_group 1;\n" ::: "memory");
        __syncthreads();

        const int row0 = tile * RPB;
        const bool full = (row0 + RPB <= B);
        const float4* sb = s4[buf];

        // ---------- per-row parent scalars (2 threads) ----------
        if (tid < RPB && (full || tid < B - row0)) {
            const float4* pb = &sb[(tid * KTOT) * RSTR];
            float np2 = 0.f;
            #pragma unroll
            for (int i = 0; i < 8; i++) {
                float4 v = pb[i];
                np2 = fmaf(v.x, v.x, fmaf(v.y, v.y, fmaf(v.z, v.z, fmaf(v.w, v.w, np2))));
            }
            const float SINH_R = 0.10016675001984403f;   // sinh(0.1)
            const float COSH_R = 1.0050041680558035f;    // cosh(0.1)
            const float EK     = 1.0100501670841680f;    // exp(0.01)

            float np      = sqrtf(np2);
            float inv_np  = __fdividef(1.0f, np);
            float sin_beta = SINH_R * 0.5f * (1.0f - np2) * inv_np;
            float cos_beta = sqrtf(fmaxf(1.0f - sin_beta * sin_beta, 0.0f));
            float hp = arcosh_fast(COSH_R * __fdividef(1.0f - np2, 1.0f + np2));

            float tmp   = __fdividef(1.0f + np, 1.0f - np);
            float ektmp = EK * tmp;
            float scale = __fdividef(ektmp - 1.0f, (ektmp + 1.0f) * np);
            float nps2  = scale * scale * np2;
            float w2    = __fdividef(2.0f, 1.0f - nps2);

            srow[tid * 2 + 0] = make_float4(inv_np, sin_beta, cos_beta, hp);
            srow[tid * 2 + 1] = make_float4(2.0f * scale, nps2, w2, 0.0f);
        }
        __syncthreads();

        // ---------- one thread per (row, child) pair ----------
        if (tid < RPB * NCH) {
            const int r = (tid >= NCH);       // 0 or 1 (RPB==2)
            const int j = tid - r * NCH;
            if (full || row0 + r < B) {
                const float4* pb = &sb[(r * KTOT) * RSTR];
                const float4* cb = &sb[(r * KTOT + 1 + j) * RSTR];

                float nc2 = 0.f, dot = 0.f;
                #pragma unroll
                for (int i = 0; i < 8; i++) {
                    float4 pv = pb[i];   // broadcast within phase
                    float4 cv = cb[i];   // stride-36 floats -> conflict-free
                    nc2 = fmaf(cv.x, cv.x, nc2); nc2 = fmaf(cv.y, cv.y, nc2);
                    nc2 = fmaf(cv.z, cv.z, nc2); nc2 = fmaf(cv.w, cv.w, nc2);
                    dot = fmaf(pv.x, cv.x, dot); dot = fmaf(pv.y, cv.y, dot);
                    dot = fmaf(pv.z, cv.z, dot); dot = fmaf(pv.w, cv.w, dot);
                }

                float4 a = srow[r * 2 + 0];   // inv_np, sin_beta, cos_beta, hp
                float4 b = srow[r * 2 + 1];   // 2*scale, nps2, 2/(1-nps2)

                float inv_nc = rsqrtf(nc2);
                float nc     = nc2 * inv_nc;

                float ca = dot * a.x * inv_nc;
                ca = fminf(fmaxf(ca, -1.0f + 1e-7f), 1.0f - 1e-7f);
                float sa = sqrtf(1.0f - ca * ca);            // sin(alpha)

                float sin_theta = sa * a.z - ca * a.y;       // sin(alpha - beta)
                float temp = 2.0f * nc * sin_theta;

                float omn     = 1.0f - nc2;
                float inv_omn = __fdividef(1.0f, omn);
                float hc = (1.0f + nc2) * rsqrtf(fmaf(omn, omn, temp * temp));
                float altitude = a.w - hc;

                float dist;
                if (altitude > 0.0f) {
                    float diff2 = fmaf(-b.x, dot, nc2 + b.y);        // |c - s*p|^2
                    float z = fmaf(b.z * diff2, inv_omn, 1.0f);
                    dist = arcosh_fast(z);
                } else {
                    float x  = temp * inv_omn;
                    float ax = fabsf(x);
                    float as = __logf(ax + sqrtf(fmaf(ax, ax, 1.0f)));
                    dist = copysignf(as, x) + 0.1f;                  // RADIUS
                }

                out[(long long)(row0 + r) * NCH + j] = dist;
            }
        }
    }
}

extern "C" void kernel_launch(void* const* d_in, const int* in_sizes, int n_in,
                              void* d_out, int out_size) {
    const float* weight = (const float*)d_in[0];
    const int*   inputs = (const int*)d_in[1];
    float*       out    = (float*)d_out;

    int B = in_sizes[1] / KTOT;                 // 16384
    int ntiles = (B + RPB - 1) / RPB;           // 8192
    int grid = ntiles < GRIDN ? ntiles : GRIDN; // 1024

    umbral_cone_kernel<<<grid, 128>>>(weight, inputs, out, B, ntiles);
}

// round 10
// speedup vs baseline: 1.1709x; 1.1709x over previous
#include <cuda_runtime.h>
#include <cuda_bf16.h>

// UmbralCone: hyperbolic cone distance.
//  weight: f32 [SIZE=100000, 32]   (d_in[0])
//  inputs: i32 [B=16384, 50]       (d_in[1])
//  out:    f32 [B, 49]
//
// Block of 128 threads handles RPB=2 batch rows (8192 full blocks):
//  Phase 1: gather 100 weight rows (128B) into padded row-major SMEM
//           (stride 9 float4 = 144B, conflict-free STS/LDS.128) via cp.async.
//  Phase 2a (OVERLAPPED): threads 0-1 load their parent row straight from
//           gmem with LDG and compute all parent scalars *while the cp.async
//           pipe drains* -> the ~300cy transcendental chain is free, and the
//           post-2a barrier disappears (one barrier per tile total).
//  Phase 2b: one thread per (row, child) pair: dot/norm from SMEM + tail.

#define RPB   2
#define KTOT  50
#define NCH   49
#define NROWS (RPB * KTOT)   // 100
#define RSTR  9              // float4 stride per row (144B)

__device__ __forceinline__ float arcosh_fast(float x) {
    x = fmaxf(x, 1.0f + 1e-7f);
    return __logf(x + sqrtf(x * x - 1.0f));
}

__device__ __forceinline__ void cp16(const float4* dst_smem, const float4* src_gmem) {
    unsigned dst = (unsigned)__cvta_generic_to_shared(dst_smem);
    asm volatile("cp.async.cg.shared.global [%0], [%1], 16;\n"
                 :: "r"(dst), "l"(src_gmem));
}

__global__ __launch_bounds__(128, 12)
void umbral_cone_kernel(const float* __restrict__ weight,
                        const int* __restrict__ inputs,
                        float* __restrict__ out,
                        int B) {
    __shared__ __align__(16) float4 s4[NROWS * RSTR];   // 14400 B
    __shared__ __align__(16) float4 srow[RPB * 2];      // per-row parent scalars

    const int tid  = threadIdx.x;
    const int row0 = blockIdx.x * RPB;
    const int g0   = tid >> 3;      // gathered-row id at u=0  (0..15)
    const int fi   = tid & 7;       // float4 lane within the 128B row
    const long long gbase = (long long)row0 * KTOT;
    const bool full = (row0 + RPB <= B);

    // ---------- Phase 1: index preload + cp.async gather ----------
    // 100 rows, 16 rows per sweep: u=0..5 full, u==6 only g0<4.
    if (full) {
        int idxv[7];
        #pragma unroll
        for (int u = 0; u < 7; u++) {
            int g = g0 + 16 * u;
            if (u < 6 || g0 < NROWS - 96)
                idxv[u] = inputs[gbase + g];
        }
        #pragma unroll
        for (int u = 0; u < 7; u++) {
            int g = g0 + 16 * u;
            if (u < 6 || g0 < NROWS - 96)
                cp16(&s4[g * RSTR + fi],
                     (const float4*)(weight + (long long)idxv[u] * 32) + fi);
        }
    } else {
        const int lim = (B - row0) * KTOT;
        #pragma unroll
        for (int u = 0; u < 7; u++) {
            int g = g0 + 16 * u;
            if (g < lim && g < NROWS) {
                int idx = inputs[gbase + g];
                cp16(&s4[g * RSTR + fi],
                     (const float4*)(weight + (long long)idx * 32) + fi);
            }
        }
    }
    asm volatile("cp.async.commit_group;\n");

    // ---------- Phase 2a: parent scalars, overlapped with async drain ----------
    // Threads 0,1 read their parent row directly from gmem (independent of the
    // cp.async pipe) and do the whole transcendental chain during the drain.
    if (tid < RPB && (full || tid < B - row0)) {
        const int pidx = inputs[gbase + tid * KTOT];
        const float4* prow = (const float4*)(weight + (long long)pidx * 32);

        float np2 = 0.f;
        #pragma unroll
        for (int i = 0; i < 8; i++) {
            float4 v = __ldg(&prow[i]);
            np2 = fmaf(v.x, v.x, fmaf(v.y, v.y, fmaf(v.z, v.z, fmaf(v.w, v.w, np2))));
        }
        const float SINH_R = 0.10016675001984403f;   // sinh(0.1)
        const float COSH_R = 1.0050041680558035f;    // cosh(0.1)
        const float EK     = 1.0100501670841680f;    // exp(0.01)

        float np      = sqrtf(np2);
        float inv_np  = __fdividef(1.0f, np);
        float sin_beta = SINH_R * 0.5f * (1.0f - np2) * inv_np;
        float cos_beta = sqrtf(fmaxf(1.0f - sin_beta * sin_beta, 0.0f));
        float hp = arcosh_fast(COSH_R * __fdividef(1.0f - np2, 1.0f + np2));

        float tmp   = __fdividef(1.0f + np, 1.0f - np);
        float ektmp = EK * tmp;
        float scale = __fdividef(ektmp - 1.0f, (ektmp + 1.0f) * np);
        float nps2  = scale * scale * np2;
        float w2    = __fdividef(2.0f, 1.0f - nps2);

        srow[tid * 2 + 0] = make_float4(inv_np, sin_beta, cos_beta, hp);
        srow[tid * 2 + 1] = make_float4(2.0f * scale, nps2, w2, 0.0f);
    }

    // Single sync point: async tile complete + srow visible.
    asm volatile("cp.async.wait_group 0;\n" ::: "memory");
    __syncthreads();

    // ---------- Phase 2b: one thread per (row, child) pair ----------
    if (tid < RPB * NCH) {
        const int r = (tid >= NCH);       // 0 or 1 (RPB==2)
        const int j = tid - r * NCH;
        if (full || row0 + r < B) {
            const float4* pb = &s4[(r * KTOT) * RSTR];
            const float4* cb = &s4[(r * KTOT + 1 + j) * RSTR];

            float nc2 = 0.f, dot = 0.f;
            #pragma unroll
            for (int i = 0; i < 8; i++) {
                float4 pv = pb[i];   // broadcast within phase
                float4 cv = cb[i];   // stride-36 floats -> conflict-free
                nc2 = fmaf(cv.x, cv.x, nc2); nc2 = fmaf(cv.y, cv.y, nc2);
                nc2 = fmaf(cv.z, cv.z, nc2); nc2 = fmaf(cv.w, cv.w, nc2);
                dot = fmaf(pv.x, cv.x, dot); dot = fmaf(pv.y, cv.y, dot);
                dot = fmaf(pv.z, cv.z, dot); dot = fmaf(pv.w, cv.w, dot);
            }

            float4 a = srow[r * 2 + 0];   // inv_np, sin_beta, cos_beta, hp
            float4 b = srow[r * 2 + 1];   // 2*scale, nps2, 2/(1-nps2)

            float inv_nc = rsqrtf(nc2);
            float nc     = nc2 * inv_nc;

            float ca = dot * a.x * inv_nc;
            ca = fminf(fmaxf(ca, -1.0f + 1e-7f), 1.0f - 1e-7f);
            float sa = sqrtf(1.0f - ca * ca);            // sin(alpha)

            float sin_theta = sa * a.z - ca * a.y;       // sin(alpha - beta)
            float temp = 2.0f * nc * sin_theta;

            float omn     = 1.0f - nc2;
            float inv_omn = __fdividef(1.0f, omn);
            float hc = (1.0f + nc2) * rsqrtf(fmaf(omn, omn, temp * temp));
            float altitude = a.w - hc;

            float dist;
            if (altitude > 0.0f) {
                float diff2 = fmaf(-b.x, dot, nc2 + b.y);        // |c - s*p|^2
                float z = fmaf(b.z * diff2, inv_omn, 1.0f);
                dist = arcosh_fast(z);
            } else {
                float x  = temp * inv_omn;
                float ax = fabsf(x);
                float as = __logf(ax + sqrtf(fmaf(ax, ax, 1.0f)));
                dist = copysignf(as, x) + 0.1f;                  // RADIUS
            }

            out[(long long)(row0 + r) * NCH + j] = dist;
        }
    }
}

extern "C" void kernel_launch(void* const* d_in, const int* in_sizes, int n_in,
                              void* d_out, int out_size) {
    const float* weight = (const float*)d_in[0];
    const int*   inputs = (const int*)d_in[1];
    float*       out    = (float*)d_out;

    int B = in_sizes[1] / KTOT;          // 16384
    int grid = (B + RPB - 1) / RPB;      // 8192

    umbral_cone_kernel<<<grid, 128>>>(weight, inputs, out, B);
}

// round 11
// speedup vs baseline: 1.2910x; 1.1026x over previous
#include <cuda_runtime.h>
#include <cuda_bf16.h>

// UmbralCone: hyperbolic cone distance.
//  weight: f32 [SIZE=100000, 32]   (d_in[0])
//  inputs: i32 [B=16384, 50]       (d_in[1])
//  out:    f32 [B, 49]
//
// Block of 128 threads handles RPB=2 batch rows (8192 full blocks):
//  Phase 1: gather 100 weight rows (128B) into padded row-major SMEM
//           (stride 9 float4 = 144B, conflict-free STS/LDS.128) via cp.async.
//  Phase 2a: 2 threads compute per-row parent scalars from SMEM.
//  Phase 2b: one thread per (row, child) pair. dot/nc2 use PACKED
//           fma.rn.f32x2 (half the issue slots of scalar FFMA; pipe
//           throughput identical -> pure issue win). arcosh/asinh tails
//           merged into a single log(A+sqrt(A*A+s)) evaluation.
//  launch_bounds(128,14) pins regs<=36 so occupancy stays ~87% (R8's FFMA2
//  attempt lost only because 38 regs / 12-block bound sank occupancy).

#define RPB   2
#define KTOT  50
#define NCH   49
#define NROWS (RPB * KTOT)   // 100
#define RSTR  9              // float4 stride per row (144B)

__device__ __forceinline__ void cp16(const float4* dst_smem, const float4* src_gmem) {
    unsigned dst = (unsigned)__cvta_generic_to_shared(dst_smem);
    asm volatile("cp.async.cg.shared.global [%0], [%1], 16;\n"
                 :: "r"(dst), "l"(src_gmem));
}

__device__ __forceinline__ void fma2(unsigned long long& acc,
                                     unsigned long long a,
                                     unsigned long long b) {
    asm("fma.rn.f32x2 %0, %1, %2, %0;" : "+l"(acc) : "l"(a), "l"(b));
}

__device__ __forceinline__ float hsum2(unsigned long long v) {
    float lo, hi;
    asm("mov.b64 {%0, %1}, %2;" : "=f"(lo), "=f"(hi) : "l"(v));
    return lo + hi;
}

__global__ __launch_bounds__(128, 14)
void umbral_cone_kernel(const float* __restrict__ weight,
                        const int* __restrict__ inputs,
                        float* __restrict__ out,
                        int B) {
    __shared__ __align__(16) float4 s4[NROWS * RSTR];   // 14400 B
    __shared__ __align__(16) float4 srow[RPB * 2];      // per-row parent scalars

    const int tid  = threadIdx.x;
    const int row0 = blockIdx.x * RPB;
    const int g0   = tid >> 3;      // gathered-row id at u=0  (0..15)
    const int fi   = tid & 7;       // float4 lane within the 128B row
    const long long gbase = (long long)row0 * KTOT;
    const bool full = (row0 + RPB <= B);

    // ---------- Phase 1: index preload + cp.async gather ----------
    // 100 rows, 16 rows per sweep: u=0..5 full, u==6 only g0<4.
    if (full) {
        int idxv[7];
        #pragma unroll
        for (int u = 0; u < 7; u++) {
            int g = g0 + 16 * u;
            if (u < 6 || g0 < NROWS - 96)
                idxv[u] = inputs[gbase + g];
        }
        #pragma unroll
        for (int u = 0; u < 7; u++) {
            int g = g0 + 16 * u;
            if (u < 6 || g0 < NROWS - 96)
                cp16(&s4[g * RSTR + fi],
                     (const float4*)(weight + (long long)idxv[u] * 32) + fi);
        }
    } else {
        const int lim = (B - row0) * KTOT;
        #pragma unroll
        for (int u = 0; u < 7; u++) {
            int g = g0 + 16 * u;
            if (g < lim && g < NROWS) {
                int idx = inputs[gbase + g];
                cp16(&s4[g * RSTR + fi],
                     (const float4*)(weight + (long long)idx * 32) + fi);
            }
        }
    }
    asm volatile("cp.async.commit_group;\n");
    asm volatile("cp.async.wait_group 0;\n" ::: "memory");
    __syncthreads();

    // ---------- Phase 2a: per-row parent scalars (2 threads) ----------
    if (tid < RPB && (full || tid < B - row0)) {
        const ulonglong2* pb = (const ulonglong2*)&s4[(tid * KTOT) * RSTR];
        unsigned long long acc = 0ull;
        #pragma unroll
        for (int i = 0; i < 8; i++) {
            ulonglong2 v = pb[i];
            fma2(acc, v.x, v.x);
            fma2(acc, v.y, v.y);
        }
        float np2 = hsum2(acc);

        const float SINH_R = 0.10016675001984403f;   // sinh(0.1)
        const float COSH_R = 1.0050041680558035f;    // cosh(0.1)
        const float EK     = 1.0100501670841680f;    // exp(0.01)

        float np      = sqrtf(np2);
        float inv_np  = __fdividef(1.0f, np);
        float sin_beta = SINH_R * 0.5f * (1.0f - np2) * inv_np;
        float cos_beta = sqrtf(fmaxf(1.0f - sin_beta * sin_beta, 0.0f));
        float zp = fmaxf(COSH_R * __fdividef(1.0f - np2, 1.0f + np2), 1.0f + 1e-7f);
        float hp = __logf(zp + sqrtf(zp * zp - 1.0f));   // arcosh

        float tmp   = __fdividef(1.0f + np, 1.0f - np);
        float ektmp = EK * tmp;
        float scale = __fdividef(ektmp - 1.0f, (ektmp + 1.0f) * np);
        float nps2  = scale * scale * np2;
        float w2    = __fdividef(2.0f, 1.0f - nps2);

        srow[tid * 2 + 0] = make_float4(inv_np, sin_beta, cos_beta, hp);
        srow[tid * 2 + 1] = make_float4(2.0f * scale, nps2, w2, 0.0f);
    }
    __syncthreads();

    // ---------- Phase 2b: one thread per (row, child) pair ----------
    if (tid < RPB * NCH) {
        const int r = (tid >= NCH);       // 0 or 1 (RPB==2)
        const int j = tid - r * NCH;
        if (full || row0 + r < B) {
            const ulonglong2* pb = (const ulonglong2*)&s4[(r * KTOT) * RSTR];
            const ulonglong2* cb = (const ulonglong2*)&s4[(r * KTOT + 1 + j) * RSTR];

            unsigned long long nc2a = 0ull, dota = 0ull;   // packed f32x2 accums
            #pragma unroll
            for (int i = 0; i < 8; i++) {
                ulonglong2 cv = cb[i];    // stride-36 floats: conflict-free
                ulonglong2 pv = pb[i];    // broadcast within warp-phase
                fma2(nc2a, cv.x, cv.x);
                fma2(nc2a, cv.y, cv.y);
                fma2(dota, pv.x, cv.x);
                fma2(dota, pv.y, cv.y);
            }
            float nc2 = hsum2(nc2a);
            float dot = hsum2(dota);

            float4 a = srow[r * 2 + 0];   // inv_np, sin_beta, cos_beta, hp
            float4 b = srow[r * 2 + 1];   // 2*scale, nps2, 2/(1-nps2)

            float inv_nc = rsqrtf(nc2);
            float nc     = nc2 * inv_nc;

            float ca = dot * a.x * inv_nc;
            ca = fminf(fmaxf(ca, -1.0f + 1e-7f), 1.0f - 1e-7f);
            float sa = sqrtf(1.0f - ca * ca);            // sin(alpha)

            float sin_theta = sa * a.z - ca * a.y;       // sin(alpha - beta)
            float temp = 2.0f * nc * sin_theta;

            float omn     = 1.0f - nc2;
            float inv_omn = __fdividef(1.0f, omn);
            float hc = (1.0f + nc2) * rsqrtf(fmaf(omn, omn, temp * temp));
            bool  up = (a.w - hc) > 0.0f;                // altitude > 0

            // Merged arcosh/asinh: both are log(A + sqrt(A*A + s)).
            float diff2 = fmaf(-b.x, dot, nc2 + b.y);            // |c - s*p|^2
            float z = fmaf(b.z * diff2, inv_omn, 1.0f);          // arcosh arg
            float x = temp * inv_omn;                            // asinh arg
            float A   = up ? fmaxf(z, 1.0f + 1e-7f) : fabsf(x);
            float sgn = up ? -1.0f : 1.0f;                       // A*A-1 vs A*A+1
            float val = __logf(A + sqrtf(fmaf(A, A, sgn)));
            float dist = up ? val : copysignf(val, x) + 0.1f;    // +RADIUS

            out[(long long)(row0 + r) * NCH + j] = dist;
        }
    }
}

extern "C" void kernel_launch(void* const* d_in, const int* in_sizes, int n_in,
                              void* d_out, int out_size) {
    const float* weight = (const float*)d_in[0];
    const int*   inputs = (const int*)d_in[1];
    float*       out    = (float*)d_out;

    int B = in_sizes[1] / KTOT;          // 16384
    int grid = (B + RPB - 1) / RPB;      // 8192

    umbral_cone_kernel<<<grid, 128>>>(weight, inputs, out, B);
}